// round 16
// baseline (speedup 1.0000x reference)
#include <cuda_runtime.h>
#include <cuda_fp16.h>
#include <cstdint>

#define ND 50000
#define NG 100000
#define NE 600000

// ---------------- static scratch ----------------
__device__ __align__(16) __half g_a_d[(size_t)ND * 64];
__device__ __align__(16) __half g_a_g[(size_t)NG * 64];
__device__ __align__(16) float  g_r_d[(size_t)ND * 64];
__device__ __align__(16) float  g_r_g[(size_t)NG * 64];
__device__ __align__(16) __half g_d1[(size_t)ND * 64];
__device__ __align__(16) __half g_g1[(size_t)NG * 64];
__device__ __align__(16) __half g_a2_d[(size_t)ND * 64];
__device__ __align__(16) __half g_a2_g[(size_t)NG * 64];
__device__ __align__(16) float  g_r2_d[(size_t)ND * 64];
__device__ __align__(16) float  g_r2_g[(size_t)NG * 64];

__device__ int g_rp_g[NG + 1];
__device__ int g_rp_d[ND + 1];
__device__ int g_cur_g[NG];
__device__ int g_cur_d[ND];
__device__ int g_col_dg[NE];
__device__ int g_col_gd[NE];
__device__ int g_bs_g[64];
__device__ int g_bs_d[64];

// ---------------- helpers ----------------
__device__ __forceinline__ uint32_t smem_u32(const void* p) {
    uint32_t a;
    asm("{ .reg .u64 t; cvta.to.shared.u64 t, %1; cvt.u32.u64 %0, t; }" : "=r"(a) : "l"(p));
    return a;
}
__device__ __forceinline__ void ldm4(uint32_t* r, uint32_t addr) {
    asm volatile("ldmatrix.sync.aligned.m8n8.x4.shared.b16 {%0,%1,%2,%3}, [%4];"
                 : "=r"(r[0]), "=r"(r[1]), "=r"(r[2]), "=r"(r[3]) : "r"(addr));
}
__device__ __forceinline__ void mma_f16(float* c, const uint32_t* a, const uint32_t* b) {
    asm volatile(
        "mma.sync.aligned.m16n8k16.row.col.f32.f16.f16.f32 "
        "{%0,%1,%2,%3}, {%4,%5,%6,%7}, {%8,%9}, {%0,%1,%2,%3};"
        : "+f"(c[0]), "+f"(c[1]), "+f"(c[2]), "+f"(c[3])
        : "r"(a[0]), "r"(a[1]), "r"(a[2]), "r"(a[3]), "r"(b[0]), "r"(b[1]));
}
__device__ __forceinline__ uint32_t h2pack(float x, float y) {
    __half2 h = __floats2half2_rn(x, y);
    return *(uint32_t*)&h;
}

// inline weight conversion: raw W -> smem fp16, padded + k-permuted.
template <int K>
__device__ __forceinline__ void convert_w(char* smem, const float* __restrict__ Wa,
                                          const float* __restrict__ Wb) {
    constexpr int ROWB = (K + 8) * 2;
    for (int i = threadIdx.x; i < 128 * K; i += 256) {
        int p = i >> 7;
        int n = i & 127;
        int blk = p >> 4, pi = p & 15;
        int lk = (blk << 4) + 4 * ((pi >> 1) & 3) + (pi & 1) + 2 * ((pi >> 3) & 1);
        float w = (n < 64) ? Wa[lk * 64 + n] : Wb[lk * 64 + (n - 64)];
        *(__half*)(smem + n * ROWB + p * 2) = __float2half_rn(w);
    }
}

// ---------------- layer-1 GEMM: [a(fp16)|r(fp32)] = X(fp32)[N,128] @ W ----------
// BLOCKS=3 (85-reg cap): 3 CTAs/SM, more warps for the L1-bound loop + real CSR overlap.
// Loads use clamped row indices (always valid); stores keep bounds checks.
template <int K, int MT, int BLOCKS>
__global__ __launch_bounds__(256, BLOCKS) void gemm_l1(
    const float* __restrict__ Xd, const float* __restrict__ Xg,
    const float* __restrict__ Wa_d, const float* __restrict__ Wb_d,
    const float* __restrict__ Wa_g, const float* __restrict__ Wb_g,
    __half* __restrict__ ad, float* __restrict__ rd,
    __half* __restrict__ ag, float* __restrict__ rg,
    int Ndis, int Ngen, int tilesD, int tilesG, int Pd) {
    constexpr int STR = K + 8;
    constexpr int ROWB = STR * 2;
    constexpr int NSTEP = K / 16;
    extern __shared__ __align__(16) char smem[];

    const float* X;
    __half* outa;
    float* outr;
    int Nrows, tbeg, tnum, tstep;
    const float *Wa, *Wb;
    if ((int)blockIdx.x < Pd) {
        X = Xd; outa = ad; outr = rd; Nrows = Ndis; Wa = Wa_d; Wb = Wb_d;
        tbeg = blockIdx.x; tnum = tilesD; tstep = Pd;
    } else {
        X = Xg; outa = ag; outr = rg; Nrows = Ngen; Wa = Wa_g; Wb = Wb_g;
        tbeg = blockIdx.x - Pd; tnum = tilesG; tstep = gridDim.x - Pd;
    }

    convert_w<K>(smem, Wa, Wb);
    __syncthreads();

    const int w = threadIdx.x >> 5, lane = threadIdx.x & 31;
    const int mw = w >> 1, nw = w & 1;
    const int g = lane >> 2, t = lane & 3;
    const uint32_t bB = smem_u32(smem) +
                        (uint32_t)((nw * 64 + ((lane >> 4) << 3) + (lane & 7)) * ROWB +
                                   ((lane >> 3) & 1) * 16);

    for (int tb = tbeg; tb < tnum; tb += tstep) {
        const int rbase = tb * (64 * MT) + mw * (16 * MT) + g;

        float c[MT][8][4];
#pragma unroll
        for (int mt = 0; mt < MT; mt++)
#pragma unroll
            for (int j = 0; j < 8; j++)
#pragma unroll
                for (int q = 0; q < 4; q++) c[mt][j][q] = 0.f;

#pragma unroll
        for (int s = 0; s < NSTEP; s++) {
            const int ke = s * 16 + 4 * t;
            uint32_t ah[MT][4];
#pragma unroll
            for (int mt = 0; mt < MT; mt++) {
                int ra = rbase + mt * 16;
                int rb = ra + 8;
                ra = (ra < Nrows) ? ra : (Nrows - 1);   // clamped, always-valid read
                rb = (rb < Nrows) ? rb : (Nrows - 1);
                float4 qa = *(const float4*)(X + (size_t)ra * K + ke);
                float4 qb = *(const float4*)(X + (size_t)rb * K + ke);
                ah[mt][0] = h2pack(qa.x, qa.y);
                ah[mt][2] = h2pack(qa.z, qa.w);
                ah[mt][1] = h2pack(qb.x, qb.y);
                ah[mt][3] = h2pack(qb.z, qb.w);
            }
            const uint32_t ko = (uint32_t)(s * 32);
#pragma unroll
            for (int p = 0; p < 4; p++) {
                uint32_t bh[4];
                ldm4(bh, bB + p * 16 * ROWB + ko);
#pragma unroll
                for (int q = 0; q < 2; q++) {
                    int j = 2 * p + q;
#pragma unroll
                    for (int mt = 0; mt < MT; mt++)
                        mma_f16(c[mt][j], ah[mt], bh + 2 * q);
                }
            }
        }

#pragma unroll
        for (int mt = 0; mt < MT; mt++) {
            const int ra = rbase + mt * 16;
            const int rb = ra + 8;
            const bool va = ra < Nrows, vb = rb < Nrows;
#pragma unroll
            for (int j = 0; j < 8; j++) {
                int col = j * 8 + 2 * t;
                if (nw == 0) {
                    if (va) *(__half2*)(outa + (size_t)ra * 64 + col) =
                        __floats2half2_rn(c[mt][j][0], c[mt][j][1]);
                    if (vb) *(__half2*)(outa + (size_t)rb * 64 + col) =
                        __floats2half2_rn(c[mt][j][2], c[mt][j][3]);
                } else {
                    if (va) *(float2*)(outr + (size_t)ra * 64 + col) =
                        make_float2(c[mt][j][0], c[mt][j][1]);
                    if (vb) *(float2*)(outr + (size_t)rb * 64 + col) =
                        make_float2(c[mt][j][2], c[mt][j][3]);
                }
            }
        }
    }
}

// ---------------- layer-2 GEMM: [a2(fp16)|r2(fp32)] = X(fp16)[N,64] @ W ----------
template <int MT, int BLOCKS>
__global__ __launch_bounds__(256, BLOCKS) void gemm_l2(
    const __half* __restrict__ Xd, const __half* __restrict__ Xg,
    const float* __restrict__ Wa_d, const float* __restrict__ Wb_d,
    const float* __restrict__ Wa_g, const float* __restrict__ Wb_g,
    __half* __restrict__ ad, float* __restrict__ rd,
    __half* __restrict__ ag, float* __restrict__ rg,
    int Ndis, int Ngen, int tilesD, int tilesG, int Pd) {
    constexpr int K = 64;
    constexpr int ROWB = (K + 8) * 2;
    constexpr int NSTEP = K / 16;
    extern __shared__ __align__(16) char smem[];

    const __half* X;
    __half* outa;
    float* outr;
    int Nrows, tbeg, tnum, tstep;
    const float *Wa, *Wb;
    if ((int)blockIdx.x < Pd) {
        X = Xd; outa = ad; outr = rd; Nrows = Ndis; Wa = Wa_d; Wb = Wb_d;
        tbeg = blockIdx.x; tnum = tilesD; tstep = Pd;
    } else {
        X = Xg; outa = ag; outr = rg; Nrows = Ngen; Wa = Wa_g; Wb = Wb_g;
        tbeg = blockIdx.x - Pd; tnum = tilesG; tstep = gridDim.x - Pd;
    }

    convert_w<K>(smem, Wa, Wb);
    __syncthreads();

    const int w = threadIdx.x >> 5, lane = threadIdx.x & 31;
    const int mw = w >> 1, nw = w & 1;
    const int g = lane >> 2, t = lane & 3;
    const uint32_t bB = smem_u32(smem) +
                        (uint32_t)((nw * 64 + ((lane >> 4) << 3) + (lane & 7)) * ROWB +
                                   ((lane >> 3) & 1) * 16);

    for (int tb = tbeg; tb < tnum; tb += tstep) {
        const int rbase = tb * (64 * MT) + mw * (16 * MT) + g;

        float c[MT][8][4];
#pragma unroll
        for (int mt = 0; mt < MT; mt++)
#pragma unroll
            for (int j = 0; j < 8; j++)
#pragma unroll
                for (int q = 0; q < 4; q++) c[mt][j][q] = 0.f;

#pragma unroll
        for (int s = 0; s < NSTEP; s++) {
            const int ke = s * 16 + 4 * t;
            uint32_t ah[MT][4];
#pragma unroll
            for (int mt = 0; mt < MT; mt++) {
                int ra = rbase + mt * 16;
                int rb = ra + 8;
                ra = (ra < Nrows) ? ra : (Nrows - 1);
                rb = (rb < Nrows) ? rb : (Nrows - 1);
                uint2 qa = *(const uint2*)(X + (size_t)ra * K + ke);
                uint2 qb = *(const uint2*)(X + (size_t)rb * K + ke);
                ah[mt][0] = qa.x;
                ah[mt][2] = qa.y;
                ah[mt][1] = qb.x;
                ah[mt][3] = qb.y;
            }
            const uint32_t ko = (uint32_t)(s * 32);
#pragma unroll
            for (int p = 0; p < 4; p++) {
                uint32_t bh[4];
                ldm4(bh, bB + p * 16 * ROWB + ko);
#pragma unroll
                for (int q = 0; q < 2; q++) {
                    int j = 2 * p + q;
#pragma unroll
                    for (int mt = 0; mt < MT; mt++)
                        mma_f16(c[mt][j], ah[mt], bh + 2 * q);
                }
            }
        }

#pragma unroll
        for (int mt = 0; mt < MT; mt++) {
            const int ra = rbase + mt * 16;
            const int rb = ra + 8;
            const bool va = ra < Nrows, vb = rb < Nrows;
#pragma unroll
            for (int j = 0; j < 8; j++) {
                int col = j * 8 + 2 * t;
                if (nw == 0) {
                    if (va) *(__half2*)(outa + (size_t)ra * 64 + col) =
                        __floats2half2_rn(c[mt][j][0], c[mt][j][1]);
                    if (vb) *(__half2*)(outa + (size_t)rb * 64 + col) =
                        __floats2half2_rn(c[mt][j][2], c[mt][j][3]);
                } else {
                    if (va) *(float2*)(outr + (size_t)ra * 64 + col) =
                        make_float2(c[mt][j][0], c[mt][j][1]);
                    if (vb) *(float2*)(outr + (size_t)rb * 64 + col) =
                        make_float2(c[mt][j][2], c[mt][j][3]);
                }
            }
        }
    }
}

// ---------------- CSR build (parallel 3-phase scan) ----------------
__global__ void zero_counts_kernel() {
    int i = blockIdx.x * blockDim.x + threadIdx.x;
    if (i < NG) g_cur_g[i] = 0;
    if (i < ND) g_cur_d[i] = 0;
}
__global__ void hist_both(const int* __restrict__ dst_dg, const int* __restrict__ dst_gd, int e) {
    int i = blockIdx.x * blockDim.x + threadIdx.x;
    if (i < e) atomicAdd(&g_cur_g[dst_dg[i]], 1);
    else if (i < 2 * e) atomicAdd(&g_cur_d[dst_gd[i - e]], 1);
}
__global__ void sbs_both(int nb_g) {
    __shared__ int sdata[256];
    int tid = threadIdx.x;
    const int* cnt;
    int n, bi;
    int* bsum;
    if (blockIdx.x < (unsigned)nb_g) { cnt = g_cur_g; n = NG; bi = blockIdx.x; bsum = g_bs_g; }
    else { cnt = g_cur_d; n = ND; bi = blockIdx.x - nb_g; bsum = g_bs_d; }
    int base = bi * 2048;
    int s = 0;
    for (int i = tid; i < 2048; i += 256) {
        int idx = base + i;
        if (idx < n) s += cnt[idx];
    }
    sdata[tid] = s;
    __syncthreads();
    for (int o = 128; o > 0; o >>= 1) {
        if (tid < o) sdata[tid] += sdata[tid + o];
        __syncthreads();
    }
    if (tid == 0) bsum[bi] = sdata[0];
}
__global__ void small_both(int nb_g, int nb_d) {
    __shared__ int s[64];
    int tid = threadIdx.x;
    int* bs = (blockIdx.x == 0) ? g_bs_g : g_bs_d;
    int nb = (blockIdx.x == 0) ? nb_g : nb_d;
    int orig = (tid < nb) ? bs[tid] : 0;
    s[tid] = orig;
    __syncthreads();
    for (int o = 1; o < 64; o <<= 1) {
        int v = (tid >= o) ? s[tid - o] : 0;
        __syncthreads();
        s[tid] += v;
        __syncthreads();
    }
    if (tid < nb) bs[tid] = s[tid] - orig;
}
__global__ void fin_both(int nb_g) {
    __shared__ int sh[256];
    int tid = threadIdx.x;
    int *cnt, *row_ptr, *cursor;
    const int* bsums;
    int n, bi;
    if (blockIdx.x < (unsigned)nb_g) {
        cnt = g_cur_g; row_ptr = g_rp_g; cursor = g_cur_g; bsums = g_bs_g; n = NG; bi = blockIdx.x;
    } else {
        cnt = g_cur_d; row_ptr = g_rp_d; cursor = g_cur_d; bsums = g_bs_d; n = ND; bi = blockIdx.x - nb_g;
    }
    int base = bi * 2048 + tid * 8;
    int v[8];
    int tsum = 0;
#pragma unroll
    for (int i = 0; i < 8; i++) {
        int idx = base + i;
        v[i] = (idx < n) ? cnt[idx] : 0;
        tsum += v[i];
    }
    sh[tid] = tsum;
    __syncthreads();
    for (int o = 1; o < 256; o <<= 1) {
        int add = (tid >= o) ? sh[tid - o] : 0;
        __syncthreads();
        sh[tid] += add;
        __syncthreads();
    }
    int run = sh[tid] - tsum + bsums[bi];
#pragma unroll
    for (int i = 0; i < 8; i++) {
        int idx = base + i;
        if (idx < n) {
            cursor[idx] = run;
            run += v[i];
            row_ptr[idx + 1] = run;
        }
    }
    if (bi == 0 && tid == 0) row_ptr[0] = 0;
}
__global__ void scatter_both(const int* __restrict__ src_dg, const int* __restrict__ dst_dg,
                             const int* __restrict__ src_gd, const int* __restrict__ dst_gd,
                             int e) {
    int i = blockIdx.x * blockDim.x + threadIdx.x;
    if (i < e) {
        int p = atomicAdd(&g_cur_g[dst_dg[i]], 1);
        g_col_dg[p] = src_dg[i];
    } else if (i < 2 * e) {
        int j = i - e;
        int p = atomicAdd(&g_cur_d[dst_gd[j]], 1);
        g_col_gd[p] = src_gd[j];
    }
}

// ---------------- fused mean-aggregate (fp16 gather, fp32 accumulate) ----------------
template <bool OUTH>
__global__ void aggregate_both(
    const __half* __restrict__ asrc_g, const float* __restrict__ rself_g,
    const float* __restrict__ bias_g, void* __restrict__ out_g,
    const __half* __restrict__ asrc_d, const float* __restrict__ rself_d,
    const float* __restrict__ bias_d, void* __restrict__ out_d,
    int gblocks) {
    const __half* asrc;
    const float *rself, *bias;
    void* out;
    const int *rp, *col;
    int ndst, t;
    if ((int)blockIdx.x < gblocks) {
        asrc = asrc_g; rself = rself_g; bias = bias_g; out = out_g;
        rp = g_rp_g; col = g_col_dg; ndst = NG;
        t = blockIdx.x * 256 + threadIdx.x;
    } else {
        asrc = asrc_d; rself = rself_d; bias = bias_d; out = out_d;
        rp = g_rp_d; col = g_col_gd; ndst = ND;
        t = (blockIdx.x - gblocks) * 256 + threadIdx.x;
    }
    int n = t >> 4;
    int l = t & 15;
    if (n >= ndst) return;
    const uint2* as2 = (const uint2*)asrc;
    int beg = rp[n], end = rp[n + 1];
    float ax = 0.f, ay = 0.f, az = 0.f, aw = 0.f;
    int e = beg;
    for (; e + 4 <= end; e += 4) {
        int c0 = __ldg(&col[e]);
        int c1 = __ldg(&col[e + 1]);
        int c2 = __ldg(&col[e + 2]);
        int c3 = __ldg(&col[e + 3]);
        uint2 u0 = as2[(size_t)c0 * 16 + l];
        uint2 u1 = as2[(size_t)c1 * 16 + l];
        uint2 u2 = as2[(size_t)c2 * 16 + l];
        uint2 u3 = as2[(size_t)c3 * 16 + l];
        float2 f0a = __half22float2(*(__half2*)&u0.x), f0b = __half22float2(*(__half2*)&u0.y);
        float2 f1a = __half22float2(*(__half2*)&u1.x), f1b = __half22float2(*(__half2*)&u1.y);
        float2 f2a = __half22float2(*(__half2*)&u2.x), f2b = __half22float2(*(__half2*)&u2.y);
        float2 f3a = __half22float2(*(__half2*)&u3.x), f3b = __half22float2(*(__half2*)&u3.y);
        ax += (f0a.x + f1a.x) + (f2a.x + f3a.x);
        ay += (f0a.y + f1a.y) + (f2a.y + f3a.y);
        az += (f0b.x + f1b.x) + (f2b.x + f3b.x);
        aw += (f0b.y + f1b.y) + (f2b.y + f3b.y);
    }
    for (; e < end; e++) {
        int c0 = __ldg(&col[e]);
        uint2 u = as2[(size_t)c0 * 16 + l];
        float2 fa = __half22float2(*(__half2*)&u.x), fb = __half22float2(*(__half2*)&u.y);
        ax += fa.x; ay += fa.y; az += fb.x; aw += fb.y;
    }
    int deg = end - beg;
    float inv = (deg > 0) ? 1.f / (float)deg : 0.f;
    float4 rs = *(const float4*)(rself + (size_t)n * 64 + l * 4);
    float4 bs = *(const float4*)(bias + l * 4);
    float ox = ax * inv + bs.x + rs.x;
    float oy = ay * inv + bs.y + rs.y;
    float oz = az * inv + bs.z + rs.z;
    float ow = aw * inv + bs.w + rs.w;
    if (OUTH) {
        uint2 o2;
        __half2 h0 = __floats2half2_rn(ox, oy);
        __half2 h1 = __floats2half2_rn(oz, ow);
        o2.x = *(uint32_t*)&h0;
        o2.y = *(uint32_t*)&h1;
        ((uint2*)out)[(size_t)n * 16 + l] = o2;
    } else {
        *(float4*)((float*)out + (size_t)n * 64 + l * 4) = make_float4(ox, oy, oz, ow);
    }
}

// ---------------- host launcher ----------------
extern "C" void kernel_launch(void* const* d_in, const int* in_sizes, int n_in,
                              void* d_out, int out_size) {
    const float* x_d = (const float*)d_in[0];
    const float* x_g = (const float*)d_in[1];
    const int* src_dg = (const int*)d_in[2];
    const int* dst_dg = (const int*)d_in[3];
    const int* src_gd = (const int*)d_in[4];
    const int* dst_gd = (const int*)d_in[5];
    const float* Wl1_dg = (const float*)d_in[6];
    const float* bl1_dg = (const float*)d_in[7];
    const float* Wr1_dg = (const float*)d_in[8];
    const float* Wl1_gd = (const float*)d_in[9];
    const float* bl1_gd = (const float*)d_in[10];
    const float* Wr1_gd = (const float*)d_in[11];
    const float* Wl2_dg = (const float*)d_in[12];
    const float* bl2_dg = (const float*)d_in[13];
    const float* Wr2_dg = (const float*)d_in[14];
    const float* Wl2_gd = (const float*)d_in[15];
    const float* bl2_gd = (const float*)d_in[16];
    const float* Wr2_gd = (const float*)d_in[17];
    float* out = (float*)d_out;

    int E = in_sizes[2];
    if (E > NE) E = NE;

    __half *ad, *ag, *d1, *g1, *a2d, *a2g;
    float *rd, *rg, *r2d, *r2g;
    cudaGetSymbolAddress((void**)&ad, g_a_d);
    cudaGetSymbolAddress((void**)&ag, g_a_g);
    cudaGetSymbolAddress((void**)&rd, g_r_d);
    cudaGetSymbolAddress((void**)&rg, g_r_g);
    cudaGetSymbolAddress((void**)&d1, g_d1);
    cudaGetSymbolAddress((void**)&g1, g_g1);
    cudaGetSymbolAddress((void**)&a2d, g_a2_d);
    cudaGetSymbolAddress((void**)&a2g, g_a2_g);
    cudaGetSymbolAddress((void**)&r2d, g_r2_d);
    cudaGetSymbolAddress((void**)&r2g, g_r2_g);

    const int t128D = (ND + 127) / 128;  // 391
    const int t128G = (NG + 127) / 128;  // 782
    const int Pd1 = 100, Pg1 = 196;
    const int Pd3 = 148, Pg3 = 296;      // gemm_l1 at 3 CTAs/SM -> 444 CTAs
    const int smem128 = 128 * (128 + 8) * 2;  // 34816
    const int smem64 = 128 * (64 + 8) * 2;    // 18432
    cudaFuncSetAttribute((const void*)gemm_l1<128, 2, 3>,
                         cudaFuncAttributeMaxDynamicSharedMemorySize, smem128);
    cudaFuncSetAttribute((const void*)gemm_l2<2, 2>,
                         cudaFuncAttributeMaxDynamicSharedMemorySize, smem64);

    const int nb_g = (NG + 2047) / 2048;  // 49
    const int nb_d = (ND + 2047) / 2048;  // 25
    const int gblocks = (NG * 16 + 255) / 256;  // 6250
    const int dblocks = (ND * 16 + 255) / 256;  // 3125

    cudaStream_t s2;
    cudaStreamCreateWithFlags(&s2, cudaStreamNonBlocking);
    cudaEvent_t eFork, eCSR;
    cudaEventCreateWithFlags(&eFork, cudaEventDisableTiming);
    cudaEventCreateWithFlags(&eCSR, cudaEventDisableTiming);

    cudaEventRecord(eFork, 0);
    cudaStreamWaitEvent(s2, eFork, 0);

    // side stream: CSR build (co-schedules with gemm_l1 at 85-reg cap)
    zero_counts_kernel<<<(NG + 255) / 256, 256, 0, s2>>>();
    hist_both<<<(2 * E + 255) / 256, 256, 0, s2>>>(dst_dg, dst_gd, E);
    sbs_both<<<nb_g + nb_d, 256, 0, s2>>>(nb_g);
    // main: layer-1 GEMM -- 4th launch (ncu-profiled)
    gemm_l1<128, 2, 3><<<Pd3 + Pg3, 256, smem128>>>(
        x_d, x_g, Wl1_dg, Wr1_gd, Wl1_gd, Wr1_dg,
        ad, rd, ag, rg, ND, NG, t128D, t128G, Pd3);
    small_both<<<2, 64, 0, s2>>>(nb_g, nb_d);
    fin_both<<<nb_g + nb_d, 256, 0, s2>>>(nb_g);
    scatter_both<<<(2 * E + 255) / 256, 256, 0, s2>>>(src_dg, dst_dg, src_gd, dst_gd, E);
    cudaEventRecord(eCSR, s2);
    cudaStreamWaitEvent(0, eCSR, 0);

    // layer-1 aggregate (fp16 gather, fp16 output)
    aggregate_both<true><<<gblocks + dblocks, 256>>>(ad, rg, bl1_dg, g1,
                                                     ag, rd, bl1_gd, d1, gblocks);

    // layer-2 transform (fp16 A direct)
    gemm_l2<2, 2><<<Pd1 + Pg1, 256, smem64>>>(
        d1, g1, Wl2_dg, Wr2_gd, Wl2_gd, Wr2_dg,
        a2d, r2d, a2g, r2g, ND, NG, t128D, t128G, Pd1);

    // layer-2 aggregate (fp16 gather, fp32 output): g2 -> out[ND*64..], d2 -> out[0..]
    aggregate_both<false><<<gblocks + dblocks, 256>>>(a2d, r2g, bl2_dg, out + (size_t)ND * 64,
                                                      a2g, r2d, bl2_gd, out, gblocks);

    cudaStreamDestroy(s2);
    cudaEventDestroy(eFork);
    cudaEventDestroy(eCSR);
}

// round 17
// speedup vs baseline: 1.6421x; 1.6421x over previous
#include <cuda_runtime.h>
#include <cuda_fp16.h>
#include <cstdint>

#define ND 50000
#define NG 100000
#define NE 600000

// ---------------- static scratch ----------------
__device__ __align__(16) __half g_a_d[(size_t)ND * 64];
__device__ __align__(16) __half g_a_g[(size_t)NG * 64];
__device__ __align__(16) float  g_r_d[(size_t)ND * 64];
__device__ __align__(16) float  g_r_g[(size_t)NG * 64];
__device__ __align__(16) __half g_d1[(size_t)ND * 64];
__device__ __align__(16) __half g_g1[(size_t)NG * 64];
__device__ __align__(16) __half g_a2_d[(size_t)ND * 64];
__device__ __align__(16) __half g_a2_g[(size_t)NG * 64];
__device__ __align__(16) float  g_r2_d[(size_t)ND * 64];
__device__ __align__(16) float  g_r2_g[(size_t)NG * 64];

__device__ int g_rp_g[NG + 1];
__device__ int g_rp_d[ND + 1];
__device__ int g_cur_g[NG];
__device__ int g_cur_d[ND];
__device__ int g_col_dg[NE];
__device__ int g_col_gd[NE];
__device__ int g_bs_g[64];
__device__ int g_bs_d[64];

// ---------------- helpers ----------------
__device__ __forceinline__ uint32_t smem_u32(const void* p) {
    uint32_t a;
    asm("{ .reg .u64 t; cvta.to.shared.u64 t, %1; cvt.u32.u64 %0, t; }" : "=r"(a) : "l"(p));
    return a;
}
__device__ __forceinline__ void ldm4(uint32_t* r, uint32_t addr) {
    asm volatile("ldmatrix.sync.aligned.m8n8.x4.shared.b16 {%0,%1,%2,%3}, [%4];"
                 : "=r"(r[0]), "=r"(r[1]), "=r"(r[2]), "=r"(r[3]) : "r"(addr));
}
__device__ __forceinline__ void mma_f16(float* c, const uint32_t* a, const uint32_t* b) {
    asm volatile(
        "mma.sync.aligned.m16n8k16.row.col.f32.f16.f16.f32 "
        "{%0,%1,%2,%3}, {%4,%5,%6,%7}, {%8,%9}, {%0,%1,%2,%3};"
        : "+f"(c[0]), "+f"(c[1]), "+f"(c[2]), "+f"(c[3])
        : "r"(a[0]), "r"(a[1]), "r"(a[2]), "r"(a[3]), "r"(b[0]), "r"(b[1]));
}
__device__ __forceinline__ uint32_t h2pack(float x, float y) {
    __half2 h = __floats2half2_rn(x, y);
    return *(uint32_t*)&h;
}

// inline weight conversion: raw W -> smem fp16, padded + k-permuted.
template <int K>
__device__ __forceinline__ void convert_w(char* smem, const float* __restrict__ Wa,
                                          const float* __restrict__ Wb) {
    constexpr int ROWB = (K + 8) * 2;
    for (int i = threadIdx.x; i < 128 * K; i += 256) {
        int p = i >> 7;
        int n = i & 127;
        int blk = p >> 4, pi = p & 15;
        int lk = (blk << 4) + 4 * ((pi >> 1) & 3) + (pi & 1) + 2 * ((pi >> 3) & 1);
        float w = (n < 64) ? Wa[lk * 64 + n] : Wb[lk * 64 + (n - 64)];
        *(__half*)(smem + n * ROWB + p * 2) = __float2half_rn(w);
    }
}

// ---------------- layer-1 GEMM: [a(fp16)|r(fp32)] = X(fp32)[N,128] @ W ----------
// R15 body (BLOCKS=2, 128 regs, no spills). Grid shaped at launch for CSR overlap.
template <int K, int MT, int BLOCKS>
__global__ __launch_bounds__(256, BLOCKS) void gemm_l1(
    const float* __restrict__ Xd, const float* __restrict__ Xg,
    const float* __restrict__ Wa_d, const float* __restrict__ Wb_d,
    const float* __restrict__ Wa_g, const float* __restrict__ Wb_g,
    __half* __restrict__ ad, float* __restrict__ rd,
    __half* __restrict__ ag, float* __restrict__ rg,
    int Ndis, int Ngen, int tilesD, int tilesG, int Pd) {
    constexpr int STR = K + 8;
    constexpr int ROWB = STR * 2;
    constexpr int NSTEP = K / 16;
    extern __shared__ __align__(16) char smem[];

    const float* X;
    __half* outa;
    float* outr;
    int Nrows, tbeg, tnum, tstep;
    const float *Wa, *Wb;
    if ((int)blockIdx.x < Pd) {
        X = Xd; outa = ad; outr = rd; Nrows = Ndis; Wa = Wa_d; Wb = Wb_d;
        tbeg = blockIdx.x; tnum = tilesD; tstep = Pd;
    } else {
        X = Xg; outa = ag; outr = rg; Nrows = Ngen; Wa = Wa_g; Wb = Wb_g;
        tbeg = blockIdx.x - Pd; tnum = tilesG; tstep = gridDim.x - Pd;
    }

    convert_w<K>(smem, Wa, Wb);
    __syncthreads();

    const int w = threadIdx.x >> 5, lane = threadIdx.x & 31;
    const int mw = w >> 1, nw = w & 1;
    const int g = lane >> 2, t = lane & 3;
    const uint32_t bB = smem_u32(smem) +
                        (uint32_t)((nw * 64 + ((lane >> 4) << 3) + (lane & 7)) * ROWB +
                                   ((lane >> 3) & 1) * 16);

    for (int tb = tbeg; tb < tnum; tb += tstep) {
        const int rbase = tb * (64 * MT) + mw * (16 * MT) + g;
        bool va[MT], vb[MT];
        const float *xa[MT], *xb[MT];
#pragma unroll
        for (int mt = 0; mt < MT; mt++) {
            int ra = rbase + mt * 16;
            va[mt] = ra < Nrows;
            vb[mt] = (ra + 8) < Nrows;
            xa[mt] = X + (size_t)ra * K + 4 * t;
            xb[mt] = X + (size_t)(ra + 8) * K + 4 * t;
        }

        float c[MT][8][4];
#pragma unroll
        for (int mt = 0; mt < MT; mt++)
#pragma unroll
            for (int j = 0; j < 8; j++)
#pragma unroll
                for (int q = 0; q < 4; q++) c[mt][j][q] = 0.f;

#pragma unroll
        for (int s = 0; s < NSTEP; s++) {
            const int ke = s * 16;
            const float4 z4 = make_float4(0.f, 0.f, 0.f, 0.f);
            uint32_t ah[MT][4];
#pragma unroll
            for (int mt = 0; mt < MT; mt++) {
                float4 qa = va[mt] ? *(const float4*)(xa[mt] + ke) : z4;
                float4 qb = vb[mt] ? *(const float4*)(xb[mt] + ke) : z4;
                ah[mt][0] = h2pack(qa.x, qa.y);
                ah[mt][2] = h2pack(qa.z, qa.w);
                ah[mt][1] = h2pack(qb.x, qb.y);
                ah[mt][3] = h2pack(qb.z, qb.w);
            }
            const uint32_t ko = (uint32_t)(s * 32);
#pragma unroll
            for (int p = 0; p < 4; p++) {
                uint32_t bh[4];
                ldm4(bh, bB + p * 16 * ROWB + ko);
#pragma unroll
                for (int q = 0; q < 2; q++) {
                    int j = 2 * p + q;
#pragma unroll
                    for (int mt = 0; mt < MT; mt++)
                        mma_f16(c[mt][j], ah[mt], bh + 2 * q);
                }
            }
        }

#pragma unroll
        for (int mt = 0; mt < MT; mt++) {
            const int ra = rbase + mt * 16;
            const int rb = ra + 8;
#pragma unroll
            for (int j = 0; j < 8; j++) {
                int col = j * 8 + 2 * t;
                if (nw == 0) {
                    if (va[mt]) *(__half2*)(outa + (size_t)ra * 64 + col) =
                        __floats2half2_rn(c[mt][j][0], c[mt][j][1]);
                    if (vb[mt]) *(__half2*)(outa + (size_t)rb * 64 + col) =
                        __floats2half2_rn(c[mt][j][2], c[mt][j][3]);
                } else {
                    if (va[mt]) *(float2*)(outr + (size_t)ra * 64 + col) =
                        make_float2(c[mt][j][0], c[mt][j][1]);
                    if (vb[mt]) *(float2*)(outr + (size_t)rb * 64 + col) =
                        make_float2(c[mt][j][2], c[mt][j][3]);
                }
            }
        }
    }
}

// ---------------- layer-2 GEMM: [a2(fp16)|r2(fp32)] = X(fp16)[N,64] @ W ----------
template <int MT, int BLOCKS>
__global__ __launch_bounds__(256, BLOCKS) void gemm_l2(
    const __half* __restrict__ Xd, const __half* __restrict__ Xg,
    const float* __restrict__ Wa_d, const float* __restrict__ Wb_d,
    const float* __restrict__ Wa_g, const float* __restrict__ Wb_g,
    __half* __restrict__ ad, float* __restrict__ rd,
    __half* __restrict__ ag, float* __restrict__ rg,
    int Ndis, int Ngen, int tilesD, int tilesG, int Pd) {
    constexpr int K = 64;
    constexpr int ROWB = (K + 8) * 2;
    constexpr int NSTEP = K / 16;
    extern __shared__ __align__(16) char smem[];

    const __half* X;
    __half* outa;
    float* outr;
    int Nrows, tbeg, tnum, tstep;
    const float *Wa, *Wb;
    if ((int)blockIdx.x < Pd) {
        X = Xd; outa = ad; outr = rd; Nrows = Ndis; Wa = Wa_d; Wb = Wb_d;
        tbeg = blockIdx.x; tnum = tilesD; tstep = Pd;
    } else {
        X = Xg; outa = ag; outr = rg; Nrows = Ngen; Wa = Wa_g; Wb = Wb_g;
        tbeg = blockIdx.x - Pd; tnum = tilesG; tstep = gridDim.x - Pd;
    }

    convert_w<K>(smem, Wa, Wb);
    __syncthreads();

    const int w = threadIdx.x >> 5, lane = threadIdx.x & 31;
    const int mw = w >> 1, nw = w & 1;
    const int g = lane >> 2, t = lane & 3;
    const uint32_t bB = smem_u32(smem) +
                        (uint32_t)((nw * 64 + ((lane >> 4) << 3) + (lane & 7)) * ROWB +
                                   ((lane >> 3) & 1) * 16);

    for (int tb = tbeg; tb < tnum; tb += tstep) {
        const int rbase = tb * (64 * MT) + mw * (16 * MT) + g;
        bool va[MT], vb[MT];
        const __half *xa[MT], *xb[MT];
#pragma unroll
        for (int mt = 0; mt < MT; mt++) {
            int ra = rbase + mt * 16;
            va[mt] = ra < Nrows;
            vb[mt] = (ra + 8) < Nrows;
            xa[mt] = X + (size_t)ra * K + 4 * t;
            xb[mt] = X + (size_t)(ra + 8) * K + 4 * t;
        }

        float c[MT][8][4];
#pragma unroll
        for (int mt = 0; mt < MT; mt++)
#pragma unroll
            for (int j = 0; j < 8; j++)
#pragma unroll
                for (int q = 0; q < 4; q++) c[mt][j][q] = 0.f;

#pragma unroll
        for (int s = 0; s < NSTEP; s++) {
            const int ke = s * 16;
            const uint2 z2 = make_uint2(0u, 0u);
            uint32_t ah[MT][4];
#pragma unroll
            for (int mt = 0; mt < MT; mt++) {
                uint2 qa = va[mt] ? *(const uint2*)(xa[mt] + ke) : z2;
                uint2 qb = vb[mt] ? *(const uint2*)(xb[mt] + ke) : z2;
                ah[mt][0] = qa.x;
                ah[mt][2] = qa.y;
                ah[mt][1] = qb.x;
                ah[mt][3] = qb.y;
            }
            const uint32_t ko = (uint32_t)(s * 32);
#pragma unroll
            for (int p = 0; p < 4; p++) {
                uint32_t bh[4];
                ldm4(bh, bB + p * 16 * ROWB + ko);
#pragma unroll
                for (int q = 0; q < 2; q++) {
                    int j = 2 * p + q;
#pragma unroll
                    for (int mt = 0; mt < MT; mt++)
                        mma_f16(c[mt][j], ah[mt], bh + 2 * q);
                }
            }
        }

#pragma unroll
        for (int mt = 0; mt < MT; mt++) {
            const int ra = rbase + mt * 16;
            const int rb = ra + 8;
#pragma unroll
            for (int j = 0; j < 8; j++) {
                int col = j * 8 + 2 * t;
                if (nw == 0) {
                    if (va[mt]) *(__half2*)(outa + (size_t)ra * 64 + col) =
                        __floats2half2_rn(c[mt][j][0], c[mt][j][1]);
                    if (vb[mt]) *(__half2*)(outa + (size_t)rb * 64 + col) =
                        __floats2half2_rn(c[mt][j][2], c[mt][j][3]);
                } else {
                    if (va[mt]) *(float2*)(outr + (size_t)ra * 64 + col) =
                        make_float2(c[mt][j][0], c[mt][j][1]);
                    if (vb[mt]) *(float2*)(outr + (size_t)rb * 64 + col) =
                        make_float2(c[mt][j][2], c[mt][j][3]);
                }
            }
        }
    }
}

// ---------------- CSR build (parallel 3-phase scan) ----------------
__global__ void hist_both(const int* __restrict__ dst_dg, const int* __restrict__ dst_gd, int e) {
    int i = blockIdx.x * blockDim.x + threadIdx.x;
    if (i < e) atomicAdd(&g_cur_g[dst_dg[i]], 1);
    else if (i < 2 * e) atomicAdd(&g_cur_d[dst_gd[i - e]], 1);
}
__global__ void sbs_both(int nb_g) {
    __shared__ int sdata[256];
    int tid = threadIdx.x;
    const int* cnt;
    int n, bi;
    int* bsum;
    if (blockIdx.x < (unsigned)nb_g) { cnt = g_cur_g; n = NG; bi = blockIdx.x; bsum = g_bs_g; }
    else { cnt = g_cur_d; n = ND; bi = blockIdx.x - nb_g; bsum = g_bs_d; }
    int base = bi * 2048;
    int s = 0;
    for (int i = tid; i < 2048; i += 256) {
        int idx = base + i;
        if (idx < n) s += cnt[idx];
    }
    sdata[tid] = s;
    __syncthreads();
    for (int o = 128; o > 0; o >>= 1) {
        if (tid < o) sdata[tid] += sdata[tid + o];
        __syncthreads();
    }
    if (tid == 0) bsum[bi] = sdata[0];
}
__global__ void small_both(int nb_g, int nb_d) {
    __shared__ int s[64];
    int tid = threadIdx.x;
    int* bs = (blockIdx.x == 0) ? g_bs_g : g_bs_d;
    int nb = (blockIdx.x == 0) ? nb_g : nb_d;
    int orig = (tid < nb) ? bs[tid] : 0;
    s[tid] = orig;
    __syncthreads();
    for (int o = 1; o < 64; o <<= 1) {
        int v = (tid >= o) ? s[tid - o] : 0;
        __syncthreads();
        s[tid] += v;
        __syncthreads();
    }
    if (tid < nb) bs[tid] = s[tid] - orig;
}
__global__ void fin_both(int nb_g) {
    __shared__ int sh[256];
    int tid = threadIdx.x;
    int *cnt, *row_ptr, *cursor;
    const int* bsums;
    int n, bi;
    if (blockIdx.x < (unsigned)nb_g) {
        cnt = g_cur_g; row_ptr = g_rp_g; cursor = g_cur_g; bsums = g_bs_g; n = NG; bi = blockIdx.x;
    } else {
        cnt = g_cur_d; row_ptr = g_rp_d; cursor = g_cur_d; bsums = g_bs_d; n = ND; bi = blockIdx.x - nb_g;
    }
    int base = bi * 2048 + tid * 8;
    int v[8];
    int tsum = 0;
#pragma unroll
    for (int i = 0; i < 8; i++) {
        int idx = base + i;
        v[i] = (idx < n) ? cnt[idx] : 0;
        tsum += v[i];
    }
    sh[tid] = tsum;
    __syncthreads();
    for (int o = 1; o < 256; o <<= 1) {
        int add = (tid >= o) ? sh[tid - o] : 0;
        __syncthreads();
        sh[tid] += add;
        __syncthreads();
    }
    int run = sh[tid] - tsum + bsums[bi];
#pragma unroll
    for (int i = 0; i < 8; i++) {
        int idx = base + i;
        if (idx < n) {
            cursor[idx] = run;
            run += v[i];
            row_ptr[idx + 1] = run;
        }
    }
    if (bi == 0 && tid == 0) row_ptr[0] = 0;
}
__global__ void scatter_both(const int* __restrict__ src_dg, const int* __restrict__ dst_dg,
                             const int* __restrict__ src_gd, const int* __restrict__ dst_gd,
                             int e) {
    int i = blockIdx.x * blockDim.x + threadIdx.x;
    if (i < e) {
        int p = atomicAdd(&g_cur_g[dst_dg[i]], 1);
        g_col_dg[p] = src_dg[i];
    } else if (i < 2 * e) {
        int j = i - e;
        int p = atomicAdd(&g_cur_d[dst_gd[j]], 1);
        g_col_gd[p] = src_gd[j];
    }
}

// ---------------- fused mean-aggregate (fp16 gather, fp32 accumulate) ----------------
template <bool OUTH>
__global__ void aggregate_both(
    const __half* __restrict__ asrc_g, const float* __restrict__ rself_g,
    const float* __restrict__ bias_g, void* __restrict__ out_g,
    const __half* __restrict__ asrc_d, const float* __restrict__ rself_d,
    const float* __restrict__ bias_d, void* __restrict__ out_d,
    int gblocks) {
    const __half* asrc;
    const float *rself, *bias;
    void* out;
    const int *rp, *col;
    int ndst, t;
    if ((int)blockIdx.x < gblocks) {
        asrc = asrc_g; rself = rself_g; bias = bias_g; out = out_g;
        rp = g_rp_g; col = g_col_dg; ndst = NG;
        t = blockIdx.x * 256 + threadIdx.x;
    } else {
        asrc = asrc_d; rself = rself_d; bias = bias_d; out = out_d;
        rp = g_rp_d; col = g_col_gd; ndst = ND;
        t = (blockIdx.x - gblocks) * 256 + threadIdx.x;
    }
    int n = t >> 4;
    int l = t & 15;
    if (n >= ndst) return;
    const uint2* as2 = (const uint2*)asrc;
    int beg = rp[n], end = rp[n + 1];
    float ax = 0.f, ay = 0.f, az = 0.f, aw = 0.f;
    int e = beg;
    for (; e + 4 <= end; e += 4) {
        int c0 = __ldg(&col[e]);
        int c1 = __ldg(&col[e + 1]);
        int c2 = __ldg(&col[e + 2]);
        int c3 = __ldg(&col[e + 3]);
        uint2 u0 = as2[(size_t)c0 * 16 + l];
        uint2 u1 = as2[(size_t)c1 * 16 + l];
        uint2 u2 = as2[(size_t)c2 * 16 + l];
        uint2 u3 = as2[(size_t)c3 * 16 + l];
        float2 f0a = __half22float2(*(__half2*)&u0.x), f0b = __half22float2(*(__half2*)&u0.y);
        float2 f1a = __half22float2(*(__half2*)&u1.x), f1b = __half22float2(*(__half2*)&u1.y);
        float2 f2a = __half22float2(*(__half2*)&u2.x), f2b = __half22float2(*(__half2*)&u2.y);
        float2 f3a = __half22float2(*(__half2*)&u3.x), f3b = __half22float2(*(__half2*)&u3.y);
        ax += (f0a.x + f1a.x) + (f2a.x + f3a.x);
        ay += (f0a.y + f1a.y) + (f2a.y + f3a.y);
        az += (f0b.x + f1b.x) + (f2b.x + f3b.x);
        aw += (f0b.y + f1b.y) + (f2b.y + f3b.y);
    }
    for (; e < end; e++) {
        int c0 = __ldg(&col[e]);
        uint2 u = as2[(size_t)c0 * 16 + l];
        float2 fa = __half22float2(*(__half2*)&u.x), fb = __half22float2(*(__half2*)&u.y);
        ax += fa.x; ay += fa.y; az += fb.x; aw += fb.y;
    }
    int deg = end - beg;
    float inv = (deg > 0) ? 1.f / (float)deg : 0.f;
    float4 rs = *(const float4*)(rself + (size_t)n * 64 + l * 4);
    float4 bs = *(const float4*)(bias + l * 4);
    float ox = ax * inv + bs.x + rs.x;
    float oy = ay * inv + bs.y + rs.y;
    float oz = az * inv + bs.z + rs.z;
    float ow = aw * inv + bs.w + rs.w;
    if (OUTH) {
        uint2 o2;
        __half2 h0 = __floats2half2_rn(ox, oy);
        __half2 h1 = __floats2half2_rn(oz, ow);
        o2.x = *(uint32_t*)&h0;
        o2.y = *(uint32_t*)&h1;
        ((uint2*)out)[(size_t)n * 16 + l] = o2;
    } else {
        *(float4*)((float*)out + (size_t)n * 64 + l * 4) = make_float4(ox, oy, oz, ow);
    }
}

// ---------------- host launcher ----------------
extern "C" void kernel_launch(void* const* d_in, const int* in_sizes, int n_in,
                              void* d_out, int out_size) {
    const float* x_d = (const float*)d_in[0];
    const float* x_g = (const float*)d_in[1];
    const int* src_dg = (const int*)d_in[2];
    const int* dst_dg = (const int*)d_in[3];
    const int* src_gd = (const int*)d_in[4];
    const int* dst_gd = (const int*)d_in[5];
    const float* Wl1_dg = (const float*)d_in[6];
    const float* bl1_dg = (const float*)d_in[7];
    const float* Wr1_dg = (const float*)d_in[8];
    const float* Wl1_gd = (const float*)d_in[9];
    const float* bl1_gd = (const float*)d_in[10];
    const float* Wr1_gd = (const float*)d_in[11];
    const float* Wl2_dg = (const float*)d_in[12];
    const float* bl2_dg = (const float*)d_in[13];
    const float* Wr2_dg = (const float*)d_in[14];
    const float* Wl2_gd = (const float*)d_in[15];
    const float* bl2_gd = (const float*)d_in[16];
    const float* Wr2_gd = (const float*)d_in[17];
    float* out = (float*)d_out;

    int E = in_sizes[2];
    if (E > NE) E = NE;

    __half *ad, *ag, *d1, *g1, *a2d, *a2g;
    float *rd, *rg, *r2d, *r2g;
    int *curg, *curd;
    cudaGetSymbolAddress((void**)&ad, g_a_d);
    cudaGetSymbolAddress((void**)&ag, g_a_g);
    cudaGetSymbolAddress((void**)&rd, g_r_d);
    cudaGetSymbolAddress((void**)&rg, g_r_g);
    cudaGetSymbolAddress((void**)&d1, g_d1);
    cudaGetSymbolAddress((void**)&g1, g_g1);
    cudaGetSymbolAddress((void**)&a2d, g_a2_d);
    cudaGetSymbolAddress((void**)&a2g, g_a2_g);
    cudaGetSymbolAddress((void**)&r2d, g_r2_d);
    cudaGetSymbolAddress((void**)&r2g, g_r2_g);
    cudaGetSymbolAddress((void**)&curg, g_cur_g);
    cudaGetSymbolAddress((void**)&curd, g_cur_d);

    const int t128D = (ND + 127) / 128;  // 391
    const int t128G = (NG + 127) / 128;  // 782
    const int PdO = 78, PgO = 154;       // 232 CTAs: ~64 SMs half-free for CSR overlap
    const int Pd1 = 100, Pg1 = 196;      // gemm_l2: full 296
    const int smem128 = 128 * (128 + 8) * 2;  // 34816
    const int smem64 = 128 * (64 + 8) * 2;    // 18432
    cudaFuncSetAttribute((const void*)gemm_l1<128, 2, 2>,
                         cudaFuncAttributeMaxDynamicSharedMemorySize, smem128);
    cudaFuncSetAttribute((const void*)gemm_l2<2, 2>,
                         cudaFuncAttributeMaxDynamicSharedMemorySize, smem64);

    const int nb_g = (NG + 2047) / 2048;  // 49
    const int nb_d = (ND + 2047) / 2048;  // 25
    const int gblocks = (NG * 16 + 255) / 256;  // 6250
    const int dblocks = (ND * 16 + 255) / 256;  // 3125

    cudaStream_t s2;
    cudaStreamCreateWithFlags(&s2, cudaStreamNonBlocking);
    cudaEvent_t eFork, eCSR;
    cudaEventCreateWithFlags(&eFork, cudaEventDisableTiming);
    cudaEventCreateWithFlags(&eCSR, cudaEventDisableTiming);

    cudaEventRecord(eFork, 0);
    cudaStreamWaitEvent(s2, eFork, 0);

    // side stream: CSR build (memset instead of zero kernel)
    cudaMemsetAsync(curg, 0, NG * sizeof(int), s2);
    cudaMemsetAsync(curd, 0, ND * sizeof(int), s2);
    hist_both<<<(2 * E + 255) / 256, 256, 0, s2>>>(dst_dg, dst_gd, E);
    sbs_both<<<nb_g + nb_d, 256, 0, s2>>>(nb_g);
    // main: layer-1 GEMM (232 CTAs -> freed SMs host CSR blocks)
    gemm_l1<128, 2, 2><<<PdO + PgO, 256, smem128>>>(
        x_d, x_g, Wl1_dg, Wr1_gd, Wl1_gd, Wr1_dg,
        ad, rd, ag, rg, ND, NG, t128D, t128G, PdO);
    small_both<<<2, 64, 0, s2>>>(nb_g, nb_d);
    fin_both<<<nb_g + nb_d, 256, 0, s2>>>(nb_g);
    scatter_both<<<(2 * E + 255) / 256, 256, 0, s2>>>(src_dg, dst_dg, src_gd, dst_gd, E);
    cudaEventRecord(eCSR, s2);
    cudaStreamWaitEvent(0, eCSR, 0);

    // layer-1 aggregate (fp16 gather, fp16 output)
    aggregate_both<true><<<gblocks + dblocks, 256>>>(ad, rg, bl1_dg, g1,
                                                     ag, rd, bl1_gd, d1, gblocks);

    // layer-2 transform (fp16 A direct)
    gemm_l2<2, 2><<<Pd1 + Pg1, 256, smem64>>>(
        d1, g1, Wl2_dg, Wr2_gd, Wl2_gd, Wr2_dg,
        a2d, r2d, a2g, r2g, ND, NG, t128D, t128G, Pd1);

    // layer-2 aggregate (fp16 gather, fp32 output): g2 -> out[ND*64..], d2 -> out[0..]
    aggregate_both<false><<<gblocks + dblocks, 256>>>(a2d, r2g, bl2_dg, out + (size_t)ND * 64,
                                                      a2g, r2d, bl2_gd, out, gblocks);

    cudaStreamDestroy(s2);
    cudaEventDestroy(eFork);
    cudaEventDestroy(eCSR);
}